// round 3
// baseline (speedup 1.0000x reference)
#include <cuda_runtime.h>
#include <math.h>

#define NP 32
#define DD 1048576
#define WDC 0.0005f
#define ALPHA_C 1.0f
#define LR_C 1e-3f

#define K1_BLOCKS 1024
#define K1_COLS (DD / K1_BLOCKS)   // 1024 columns per block
#define TILE_K 32

// Scratch (static device arrays; no runtime allocation)
__device__ float g_part[(size_t)K1_BLOCKS * 3 * NP * NP];  // per-block Gram partials
__device__ float g_gram[3 * NP * NP];                      // XX, XR, RR (row-major i*32+j)
__device__ float g_UT[NP * NP];                            // U transposed: [j][i]
__device__ float g_VT[NP * NP];                            // V transposed: [j][i]

// ---------------------------------------------------------------------------
// Kernel 1: per-block partial Gram matrices XX, XR, RR over a column slice.
// blockDim = (32, 8). Warp w owns i-rows {4w..4w+3} (smem broadcasts),
// lane owns j. Deterministic (no atomics).
// ---------------------------------------------------------------------------
__global__ __launch_bounds__(256) void k_gram(const float* __restrict__ X,
                                              const float* __restrict__ R) {
    __shared__ float Xs[32][33];
    __shared__ float Rs[32][33];

    const int lane = threadIdx.x;            // j
    const int w    = threadIdx.y;            // warp id
    const int lt   = w * 32 + lane;          // 0..255
    const int lrow = lt >> 3;                // 0..31 (load row)
    const int lq4  = (lt & 7) * 4;           // 0,4,..28 (load quad)
    const int i0   = w * 4;

    const size_t base = (size_t)blockIdx.x * K1_COLS;

    float aXX[4], aXR[4], aRR[4];
#pragma unroll
    for (int c = 0; c < 4; c++) { aXX[c] = 0.f; aXR[c] = 0.f; aRR[c] = 0.f; }

    for (int t = 0; t < K1_COLS; t += TILE_K) {
        const float4 xv = *(const float4*)(X + (size_t)lrow * DD + base + t + lq4);
        const float4 rv = *(const float4*)(R + (size_t)lrow * DD + base + t + lq4);
        __syncthreads();   // previous tile fully consumed
        Xs[lrow][lq4 + 0] = xv.x; Xs[lrow][lq4 + 1] = xv.y;
        Xs[lrow][lq4 + 2] = xv.z; Xs[lrow][lq4 + 3] = xv.w;
        Rs[lrow][lq4 + 0] = rv.x; Rs[lrow][lq4 + 1] = rv.y;
        Rs[lrow][lq4 + 2] = rv.z; Rs[lrow][lq4 + 3] = rv.w;
        __syncthreads();

#pragma unroll 8
        for (int k = 0; k < TILE_K; k++) {
            const float xj = Xs[lane][k];
            const float rj = Rs[lane][k];
#pragma unroll
            for (int c = 0; c < 4; c++) {
                const float xi = Xs[i0 + c][k];   // warp broadcast
                const float ri = Rs[i0 + c][k];   // warp broadcast
                aXX[c] += xi * xj;
                aXR[c] += xi * rj;
                aRR[c] += ri * rj;
            }
        }
    }

    float* p = g_part + (size_t)blockIdx.x * (3 * NP * NP);
#pragma unroll
    for (int c = 0; c < 4; c++) {
        const int i = i0 + c;
        p[           i * 32 + lane] = aXX[c];
        p[1024 +     i * 32 + lane] = aXR[c];
        p[2048 +     i * 32 + lane] = aRR[c];
    }
}

// ---------------------------------------------------------------------------
// Kernel 1b: deterministic reduction of partials -> g_gram.
// grid = 96 blocks x 256 threads; each block produces 32 outputs,
// 8 partial-streams per output, tree-combined via smem.
// ---------------------------------------------------------------------------
__global__ __launch_bounds__(256) void k_reduce() {
    __shared__ float red[8][33];
    const int part = threadIdx.x >> 5;               // 0..7
    const int jj   = threadIdx.x & 31;
    const int o    = blockIdx.x * 32 + jj;           // 0..3071

    const int per = K1_BLOCKS / 8;                   // 128
    const int b0  = part * per;
    float s0 = 0.f, s1 = 0.f, s2 = 0.f, s3 = 0.f;
#pragma unroll 4
    for (int b = 0; b < per; b += 4) {
        s0 += g_part[(size_t)(b0 + b + 0) * 3072 + o];
        s1 += g_part[(size_t)(b0 + b + 1) * 3072 + o];
        s2 += g_part[(size_t)(b0 + b + 2) * 3072 + o];
        s3 += g_part[(size_t)(b0 + b + 3) * 3072 + o];
    }
    red[part][jj] = (s0 + s1) + (s2 + s3);
    __syncthreads();
    if (part == 0) {
        float s = 0.f;
#pragma unroll
        for (int pth = 0; pth < 8; pth++) s += red[pth][jj];
        g_gram[o] = s;
    }
}

// ---------------------------------------------------------------------------
// Kernel 2: single block, 1024 threads (t -> i=t/32, j=t%32).
// Builds U, V (32x32) from the Gram matrices:
//   out = X + clip( U @ X + V @ R , +-1000 )
// All scaling (LR, 1/n, alpha*sign(gloss), epoch<150 expansion) folded in.
// ---------------------------------------------------------------------------
__global__ __launch_bounds__(1024) void k_small(const float* __restrict__ gloss,
                                                const int* __restrict__ epoch_p) {
    __shared__ float sXX[1024], sXR[1024], sRR[1024];
    __shared__ float sXG[1024], sGG[1024], sPD[1024];
    __shared__ float sSq[32], sGn2[32], sdXG[32], sCoef[32];
    __shared__ float sRowC[32], sRowK[32], sRowA[32];
    __shared__ float sMed[2];

    const int t = threadIdx.x;
    const int i = t >> 5;
    const int j = t & 31;

    int eraw = *epoch_p;
    // hedge: if the scalar arrived as a float bit-pattern, decode it
    if (eraw > 1000000 || eraw < 0) eraw = (int)__int_as_float(eraw);
    const bool late = (eraw >= 150);

    sXX[t] = g_gram[t];
    sXR[t] = g_gram[1024 + t];
    sRR[t] = g_gram[2048 + t];
    __syncthreads();

    float xg, gg;
    if (late) { xg = sXR[t]; gg = sRR[t]; }
    else {
        xg = sXR[t] + WDC * sXX[t];
        gg = sRR[t] + WDC * (sXR[t] + sXR[j * 32 + i]) + WDC * WDC * sXX[t];
    }
    sXG[t] = xg; sGG[t] = gg;
    __syncthreads();

    if (t < 32) {
        sSq[t]   = sXX[t * 33];
        sGn2[t]  = sGG[t * 33];
        sdXG[t]  = sXG[t * 33];
        // coef (only used when late): (lpg_i . g_i)/||g_i||^2 with g = r
        sCoef[t] = (sRR[t * 33] + WDC * sXR[t * 33]) / sGG[t * 33];
    }
    __syncthreads();

    const float pd = fmaxf(sSq[i] + sSq[j] - 2.f * sXX[t], 0.f);
    sPD[t] = pd;
    __syncthreads();

    // median of 1024 values = mean of order stats 511, 512 (0-indexed),
    // found by rank counting (smem broadcast reads).
    int less = 0, leq = 0;
    const float4* p4 = (const float4*)sPD;
#pragma unroll 4
    for (int s = 0; s < 256; s++) {
        const float4 v = p4[s];
        less += (v.x <  pd) + (v.y <  pd) + (v.z <  pd) + (v.w <  pd);
        leq  += (v.x <= pd) + (v.y <= pd) + (v.z <= pd) + (v.w <= pd);
    }
    if (less <= 511 && 511 < leq) sMed[0] = pd;
    if (less <= 512 && 512 < leq) sMed[1] = pd;
    __syncthreads();

    const float hk = (sMed[0] + sMed[1]) * 0.5f / 3.4657359027997265f + 1e-6f;
    const float Kv = expf(-pd / hk);
    const float Cv = 2.f * Kv / hk;

    // A and row reductions (warp == one i-row)
    const float Av = Cv * (sdXG[i] - sXG[j * 32 + i]) / sGn2[i];
    float rc = Cv, rk = Kv, ra = Av;
#pragma unroll
    for (int off = 16; off; off >>= 1) {
        rc += __shfl_xor_sync(0xffffffffu, rc, off);
        rk += __shfl_xor_sync(0xffffffffu, rk, off);
        ra += __shfl_xor_sync(0xffffffffu, ra, off);
    }
    if (j == 0) { sRowC[i] = rc; sRowK[i] = rk; sRowA[i] = ra; }

    const float Bv = (Cv * (xg - sdXG[j]) - Av * gg) / sGn2[j];
    float Mv = 0.f;
    if (late) {
        const float coef = sCoef[i];
        const float sgt  = WDC * xg + (1.f - coef) * gg;  // S_i . g_j
        Mv = Kv * sgt / sGn2[j];
    }
    __syncthreads();

    float Ux = -Cv;
    float Vg = -Bv - Mv;
    if (i == j) {
        Ux += sRowC[i] + (late ? WDC * sRowK[i] : 0.f);
        Vg += -sRowA[i] + (late ? (1.f - sCoef[i]) * sRowK[i] : 0.f);
    }
    const float sc = LR_C / (float)NP;
    float U = Ux * sc;
    float V = Vg * sc;
    if (i == j) {
        const float gl = gloss[i];
        const float sg = (gl > 0.f) ? 1.f : ((gl < 0.f) ? -1.f : 0.f);
        V -= LR_C * ALPHA_C * sg;
    }
    if (!late) U += WDC * V;   // expand g_j = r_j + WD*x_j

    g_UT[j * 32 + i] = U;
    g_VT[j * 32 + i] = V;
}

// ---------------------------------------------------------------------------
// Kernel 3: out = X + clip(U@X + V@R).  grid = D/256 blocks x 256 threads.
// Each block owns 256 columns; thread (ig,q) computes 8 output rows for one
// float4 column group. Coefficient reads are pure warp broadcasts from smem.
// ---------------------------------------------------------------------------
__global__ __launch_bounds__(256) void k_apply(const float* __restrict__ X,
                                               const float* __restrict__ R,
                                               float* __restrict__ out) {
    __shared__ float sUT[1024], sVT[1024];
    const int tid = threadIdx.x;
    for (int s = tid; s < 1024; s += 256) { sUT[s] = g_UT[s]; sVT[s] = g_VT[s]; }
    __syncthreads();

    const int ig = tid >> 6;                    // 0..3 -> i rows [8*ig, 8*ig+8)
    const int q  = tid & 63;
    const size_t col = ((size_t)blockIdx.x * 64 + q) * 4;

    float acc[8][4];
#pragma unroll
    for (int s = 0; s < 8; s++)
#pragma unroll
        for (int d = 0; d < 4; d++) acc[s][d] = 0.f;

#pragma unroll 2
    for (int j = 0; j < 32; j++) {
        const float4 xv = *(const float4*)(X + (size_t)j * DD + col);
        const float4 rv = *(const float4*)(R + (size_t)j * DD + col);
#pragma unroll
        for (int s = 0; s < 8; s++) {
            const int i = ig * 8 + s;
            const float u = sUT[j * 32 + i];   // warp broadcast
            const float v = sVT[j * 32 + i];   // warp broadcast
            acc[s][0] += u * xv.x + v * rv.x;
            acc[s][1] += u * xv.y + v * rv.y;
            acc[s][2] += u * xv.z + v * rv.z;
            acc[s][3] += u * xv.w + v * rv.w;
        }
    }

#pragma unroll
    for (int s = 0; s < 8; s++) {
        const int i = ig * 8 + s;
        const float4 xv = *(const float4*)(X + (size_t)i * DD + col);  // L1 hit
        float4 o;
        o.x = xv.x + fminf(fmaxf(acc[s][0], -1000.f), 1000.f);
        o.y = xv.y + fminf(fmaxf(acc[s][1], -1000.f), 1000.f);
        o.z = xv.z + fminf(fmaxf(acc[s][2], -1000.f), 1000.f);
        o.w = xv.w + fminf(fmaxf(acc[s][3], -1000.f), 1000.f);
        *(float4*)(out + (size_t)i * DD + col) = o;
    }
}

// ---------------------------------------------------------------------------
extern "C" void kernel_launch(void* const* d_in, const int* in_sizes, int n_in,
                              void* d_out, int out_size) {
    const float* X  = (const float*)d_in[0];   // particles [32, 1048576]
    const float* R  = (const float*)d_in[1];   // raw_grad  [32, 1048576]
    const float* gl = (const float*)d_in[2];   // gloss [32]
    const int*   ep = (const int*)d_in[3];     // epoch scalar
    float* out = (float*)d_out;

    k_gram<<<K1_BLOCKS, dim3(32, 8)>>>(X, R);
    k_reduce<<<96, 256>>>();
    k_small<<<1, 1024>>>(gl, ep);
    k_apply<<<DD / 256, 256>>>(X, R, out);
}

// round 6
// speedup vs baseline: 1.2341x; 1.2341x over previous
#include <cuda_runtime.h>
#include <cuda_bf16.h>
#include <math.h>
#include <cstdint>

#define NP 32
#define DD 1048576
#define WDC 0.0005f
#define ALPHA_C 1.0f
#define LR_C 1e-3f

// ---- Gram (mma.sync bf16) config ----
#define GCTA 512                 // CTAs for gram
#define KLOC (DD / GCTA)         // 2048 K per CTA
#define CHUNK 64                 // K columns per staged chunk (128B bf16 rows)
#define NCH (KLOC / CHUNK)       // 32 chunks
#define NPART (GCTA * 2)         // partial blocks (2 K-halves per CTA)

// Scratch (static device arrays; no runtime allocation)
__device__ float g_part2[(size_t)NPART * 64 * 64]; // per-(CTA,half) 64x64 partials
__device__ float g_gram[3 * NP * NP];              // XX, XR, RR (row-major i*32+j)
__device__ float g_UT[NP * NP];                    // U transposed: [j][i]
__device__ float g_VT[NP * NP];                    // V transposed: [j][i]

// row-major 64 x 128B bf16 tile, XOR-16B swizzle keyed on row&7.
// byte(row, bf16col) = row*128 + ((2*col) ^ ((row&7)<<4))
__device__ __forceinline__ uint32_t tile_byte(int row, int col2 /*=2*col*/) {
    return (uint32_t)(row * 128 + (col2 ^ ((row & 7) << 4)));
}

__device__ __forceinline__ void mma_bf16(float* d, uint32_t a0, uint32_t a1,
                                         uint32_t a2, uint32_t a3,
                                         uint32_t b0, uint32_t b1) {
    asm volatile(
        "mma.sync.aligned.m16n8k16.row.col.f32.bf16.bf16.f32 "
        "{%0,%1,%2,%3}, {%4,%5,%6,%7}, {%8,%9}, {%0,%1,%2,%3};"
        : "+f"(d[0]), "+f"(d[1]), "+f"(d[2]), "+f"(d[3])
        : "r"(a0), "r"(a1), "r"(a2), "r"(a3), "r"(b0), "r"(b1));
}

// ---------------------------------------------------------------------------
// Kernel 1: bf16 Gram via mma.sync. CTA computes P.P^T (P=[X;R], 64 rows)
// over its K-slice. 8 warps = 4 M-strips (16 rows) x 2 K-halves (32 k each
// per 64-chunk). D accumulates in registers across 32 chunks; each warp
// writes its 16x64 partial strip (per K-half) to g_part2.
// ---------------------------------------------------------------------------
__global__ __launch_bounds__(256) void k_gram_mma(const float* __restrict__ X,
                                                  const float* __restrict__ R) {
    __shared__ __align__(16) char s_tile[2][64 * 128];

    const int tid  = threadIdx.x;
    const int lane = tid & 31;
    const int w    = tid >> 5;       // warp 0..7
    const int m    = w & 3;          // M-strip (rows 16m..16m+15)
    const int h    = w >> 2;         // K-half (k 32h..32h+31 within chunk)
    const int grp  = lane >> 2;      // 0..7
    const int th4  = lane & 3;       // 0..3

    // staging role: thread owns P row r, quad q; 16 floats per chunk
    const int r = tid >> 2;          // 0..63
    const int q = tid & 3;
    const size_t base = (size_t)blockIdx.x * KLOC;
    const float* src = (r < 32 ? X + (size_t)r * DD : R + (size_t)(r - 32) * DD) + base;

    float d[8][4];
#pragma unroll
    for (int n = 0; n < 8; n++)
#pragma unroll
        for (int e = 0; e < 4; e++) d[n][e] = 0.f;

    // prefetch chunk 0
    float4 v[4];
#pragma unroll
    for (int s = 0; s < 4; s++) v[s] = *(const float4*)(src + q * 4 + s * 16);

    // store chunk 0 into buffer 0
#pragma unroll
    for (int s = 0; s < 4; s++) {
        __nv_bfloat162 ab = __float22bfloat162_rn(make_float2(v[s].x, v[s].y));
        __nv_bfloat162 cd = __float22bfloat162_rn(make_float2(v[s].z, v[s].w));
        unsigned long long pk = (unsigned long long)(*(uint32_t*)&ab) |
                                ((unsigned long long)(*(uint32_t*)&cd) << 32);
        *(unsigned long long*)(s_tile[0] + tile_byte(r, q * 8 + s * 32)) = pk;
    }
    __syncthreads();

    for (int c = 0; c < NCH; c++) {
        const int buf = c & 1;

        // issue next chunk's global loads (in flight during mma)
        if (c + 1 < NCH) {
            const float* p = src + (c + 1) * CHUNK;
#pragma unroll
            for (int s = 0; s < 4; s++) v[s] = *(const float4*)(p + q * 4 + s * 16);
        }

        // compute on buf
        const char* tb = s_tile[buf];
#pragma unroll
        for (int step = 0; step < 2; step++) {
            const int k0 = h * 32 + step * 16;          // k base (bf16 col)
            const int row0 = 16 * m + grp;
            const int colA2 = (k0 + th4 * 2) * 2;       // byte col (before swizzle)
            const uint32_t a0 = *(const uint32_t*)(tb + tile_byte(row0,     colA2));
            const uint32_t a1 = *(const uint32_t*)(tb + tile_byte(row0 + 8, colA2));
            const uint32_t a2 = *(const uint32_t*)(tb + tile_byte(row0,     colA2 + 16));
            const uint32_t a3 = *(const uint32_t*)(tb + tile_byte(row0 + 8, colA2 + 16));
#pragma unroll
            for (int n = 0; n < 8; n++) {
                const int brow = 8 * n + grp;
                const uint32_t b0 = *(const uint32_t*)(tb + tile_byte(brow, colA2));
                const uint32_t b1 = *(const uint32_t*)(tb + tile_byte(brow, colA2 + 16));
                mma_bf16(d[n], a0, a1, a2, a3, b0, b1);
            }
        }

        // stage next chunk into the other buffer
        if (c + 1 < NCH) {
            char* nb = s_tile[buf ^ 1];
#pragma unroll
            for (int s = 0; s < 4; s++) {
                __nv_bfloat162 ab = __float22bfloat162_rn(make_float2(v[s].x, v[s].y));
                __nv_bfloat162 cd = __float22bfloat162_rn(make_float2(v[s].z, v[s].w));
                unsigned long long pk = (unsigned long long)(*(uint32_t*)&ab) |
                                        ((unsigned long long)(*(uint32_t*)&cd) << 32);
                *(unsigned long long*)(nb + tile_byte(r, q * 8 + s * 32)) = pk;
            }
        }
        __syncthreads();
    }

    // write partial: block (blockIdx*2 + h), rows 16m..16m+15, cols 0..63
    float* p = g_part2 + ((size_t)blockIdx.x * 2 + h) * 4096;
#pragma unroll
    for (int n = 0; n < 8; n++) {
        const int row = 16 * m + grp;
        const int col = 8 * n + th4 * 2;
        *(float2*)(p + row * 64 + col)       = make_float2(d[n][0], d[n][1]);
        *(float2*)(p + (row + 8) * 64 + col) = make_float2(d[n][2], d[n][3]);
    }
}

// ---------------------------------------------------------------------------
// Kernel 1b: reduce 1024 64x64 partials -> g_gram (XX/XR/RR 32x32 blocks).
// grid = 96 x 256; 8 partial-streams of 128 each, tree-combined. Deterministic.
// ---------------------------------------------------------------------------
__global__ __launch_bounds__(256) void k_reduce() {
    __shared__ float red[8][33];
    const int part = threadIdx.x >> 5;
    const int jj   = threadIdx.x & 31;
    const int o    = blockIdx.x * 32 + jj;          // 0..3071
    const int mtx  = o >> 10;                        // 0=XX 1=XR 2=RR
    const int i    = (o >> 5) & 31;
    const int j    = o & 31;
    const int src  = (mtx == 0) ? (i * 64 + j)
                   : (mtx == 1) ? (i * 64 + 32 + j)
                                : ((32 + i) * 64 + 32 + j);

    const int per = NPART / 8;                       // 128
    const int b0  = part * per;
    float s0 = 0.f, s1 = 0.f, s2 = 0.f, s3 = 0.f;
#pragma unroll 4
    for (int b = 0; b < per; b += 4) {
        s0 += g_part2[(size_t)(b0 + b + 0) * 4096 + src];
        s1 += g_part2[(size_t)(b0 + b + 1) * 4096 + src];
        s2 += g_part2[(size_t)(b0 + b + 2) * 4096 + src];
        s3 += g_part2[(size_t)(b0 + b + 3) * 4096 + src];
    }
    red[part][jj] = (s0 + s1) + (s2 + s3);
    __syncthreads();
    if (part == 0) {
        float s = 0.f;
#pragma unroll
        for (int pth = 0; pth < 8; pth++) s += red[pth][jj];
        g_gram[o] = s;
    }
}

// ---------------------------------------------------------------------------
// Kernel 2: build U, V (32x32):  out = X + clip(U@X + V@R, +-1000)
// ---------------------------------------------------------------------------
__global__ __launch_bounds__(1024) void k_small(const float* __restrict__ gloss,
                                                const int* __restrict__ epoch_p) {
    __shared__ float sXX[1024], sXR[1024], sRR[1024];
    __shared__ float sXG[1024], sGG[1024], sPD[1024];
    __shared__ float sSq[32], sGn2[32], sdXG[32], sCoef[32];
    __shared__ float sRowC[32], sRowK[32], sRowA[32];
    __shared__ float sMed[2];

    const int t = threadIdx.x;
    const int i = t >> 5;
    const int j = t & 31;

    int eraw = *epoch_p;
    if (eraw > 1000000 || eraw < 0) eraw = (int)__int_as_float(eraw);
    const bool late = (eraw >= 150);

    sXX[t] = g_gram[t];
    sXR[t] = g_gram[1024 + t];
    sRR[t] = g_gram[2048 + t];
    __syncthreads();

    float xg, gg;
    if (late) { xg = sXR[t]; gg = sRR[t]; }
    else {
        xg = sXR[t] + WDC * sXX[t];
        gg = sRR[t] + WDC * (sXR[t] + sXR[j * 32 + i]) + WDC * WDC * sXX[t];
    }
    sXG[t] = xg; sGG[t] = gg;
    __syncthreads();

    if (t < 32) {
        sSq[t]   = sXX[t * 33];
        sGn2[t]  = sGG[t * 33];
        sdXG[t]  = sXG[t * 33];
        sCoef[t] = (sRR[t * 33] + WDC * sXR[t * 33]) / sGG[t * 33];
    }
    __syncthreads();

    const float pd = fmaxf(sSq[i] + sSq[j] - 2.f * sXX[t], 0.f);
    sPD[t] = pd;
    __syncthreads();

    int less = 0, leq = 0;
    const float4* p4 = (const float4*)sPD;
#pragma unroll 4
    for (int s = 0; s < 256; s++) {
        const float4 v = p4[s];
        less += (v.x <  pd) + (v.y <  pd) + (v.z <  pd) + (v.w <  pd);
        leq  += (v.x <= pd) + (v.y <= pd) + (v.z <= pd) + (v.w <= pd);
    }
    if (less <= 511 && 511 < leq) sMed[0] = pd;
    if (less <= 512 && 512 < leq) sMed[1] = pd;
    __syncthreads();

    const float hk = (sMed[0] + sMed[1]) * 0.5f / 3.4657359027997265f + 1e-6f;
    const float Kv = expf(-pd / hk);
    const float Cv = 2.f * Kv / hk;

    const float Av = Cv * (sdXG[i] - sXG[j * 32 + i]) / sGn2[i];
    float rc = Cv, rk = Kv, ra = Av;
#pragma unroll
    for (int off = 16; off; off >>= 1) {
        rc += __shfl_xor_sync(0xffffffffu, rc, off);
        rk += __shfl_xor_sync(0xffffffffu, rk, off);
        ra += __shfl_xor_sync(0xffffffffu, ra, off);
    }
    if (j == 0) { sRowC[i] = rc; sRowK[i] = rk; sRowA[i] = ra; }

    const float Bv = (Cv * (xg - sdXG[j]) - Av * gg) / sGn2[j];
    float Mv = 0.f;
    if (late) {
        const float coef = sCoef[i];
        const float sgt  = WDC * xg + (1.f - coef) * gg;
        Mv = Kv * sgt / sGn2[j];
    }
    __syncthreads();

    float Ux = -Cv;
    float Vg = -Bv - Mv;
    if (i == j) {
        Ux += sRowC[i] + (late ? WDC * sRowK[i] : 0.f);
        Vg += -sRowA[i] + (late ? (1.f - sCoef[i]) * sRowK[i] : 0.f);
    }
    const float sc = LR_C / (float)NP;
    float U = Ux * sc;
    float V = Vg * sc;
    if (i == j) {
        const float gl = gloss[i];
        const float sg = (gl > 0.f) ? 1.f : ((gl < 0.f) ? -1.f : 0.f);
        V -= LR_C * ALPHA_C * sg;
    }
    if (!late) U += WDC * V;

    g_UT[j * 32 + i] = U;
    g_VT[j * 32 + i] = V;
}

// ---------------------------------------------------------------------------
// Kernel 3: out = X + clip(U@X + V@R). 4 rows x float4 per thread.
// ---------------------------------------------------------------------------
__global__ __launch_bounds__(256) void k_apply(const float* __restrict__ X,
                                               const float* __restrict__ R,
                                               float* __restrict__ out) {
    __shared__ float sUT[1024], sVT[1024];
    const int tid = threadIdx.x;
    for (int s = tid; s < 1024; s += 256) { sUT[s] = g_UT[s]; sVT[s] = g_VT[s]; }
    __syncthreads();

    const int ig = tid >> 5;                       // 0..7 -> rows [4*ig, 4*ig+4)
    const int q  = tid & 31;
    const size_t col = ((size_t)blockIdx.x * 32 + q) * 4;

    float acc[4][4];
#pragma unroll
    for (int s = 0; s < 4; s++)
#pragma unroll
        for (int d = 0; d < 4; d++) acc[s][d] = 0.f;

#pragma unroll 4
    for (int j = 0; j < 32; j++) {
        const float4 xv = *(const float4*)(X + (size_t)j * DD + col);
        const float4 rv = *(const float4*)(R + (size_t)j * DD + col);
#pragma unroll
        for (int s = 0; s < 4; s++) {
            const int i = ig * 4 + s;
            const float u = sUT[j * 32 + i];       // warp broadcast
            const float v = sVT[j * 32 + i];       // warp broadcast
            acc[s][0] += u * xv.x + v * rv.x;
            acc[s][1] += u * xv.y + v * rv.y;
            acc[s][2] += u * xv.z + v * rv.z;
            acc[s][3] += u * xv.w + v * rv.w;
        }
    }

#pragma unroll
    for (int s = 0; s < 4; s++) {
        const int i = ig * 4 + s;
        const float4 xv = *(const float4*)(X + (size_t)i * DD + col);
        float4 o;
        o.x = xv.x + fminf(fmaxf(acc[s][0], -1000.f), 1000.f);
        o.y = xv.y + fminf(fmaxf(acc[s][1], -1000.f), 1000.f);
        o.z = xv.z + fminf(fmaxf(acc[s][2], -1000.f), 1000.f);
        o.w = xv.w + fminf(fmaxf(acc[s][3], -1000.f), 1000.f);
        *(float4*)(out + (size_t)i * DD + col) = o;
    }
}

// ---------------------------------------------------------------------------
extern "C" void kernel_launch(void* const* d_in, const int* in_sizes, int n_in,
                              void* d_out, int out_size) {
    const float* X  = (const float*)d_in[0];
    const float* R  = (const float*)d_in[1];
    const float* gl = (const float*)d_in[2];
    const int*   ep = (const int*)d_in[3];
    float* out = (float*)d_out;

    k_gram_mma<<<GCTA, 256>>>(X, R);
    k_reduce<<<96, 256>>>();
    k_small<<<1, 1024>>>(gl, ep);
    k_apply<<<DD / 128, 256>>>(X, R, out);
}

// round 9
// speedup vs baseline: 1.5012x; 1.2164x over previous
#include <cuda_runtime.h>
#include <cuda_bf16.h>
#include <math.h>
#include <cstdint>

#define NP 32
#define DD 1048576
#define WDC 0.0005f
#define ALPHA_C 1.0f
#define LR_C 1e-3f

// ---- Gram (mma.sync bf16) config ----
#define GCTA 512                 // CTAs for gram
#define KLOC (DD / GCTA)         // 2048 K per CTA
#define CHUNK 64                 // K columns per staged chunk (128B bf16 rows)
#define NCH (KLOC / CHUNK)       // 32 chunks
#define NPART (GCTA * 2)         // partial blocks (2 K-halves per CTA)

// Scratch (static device arrays; no runtime allocation)
__device__ float g_part2[(size_t)NPART * 64 * 64]; // per-(CTA,half) 64x64 partials
__device__ float g_gram[3 * NP * NP];              // XX, XR, RR (row-major i*32+j)
__device__ float g_UT[NP * NP];                    // U transposed: [j][i]
__device__ float g_VT[NP * NP];                    // V transposed: [j][i]

// row-major 64 x 128B bf16 tile, XOR-16B swizzle keyed on row&7.
__device__ __forceinline__ uint32_t tile_byte(int row, int col2 /*=2*col*/) {
    return (uint32_t)(row * 128 + (col2 ^ ((row & 7) << 4)));
}
// row-major 256B-row bf16 tile (apply B tile), same swizzle idea
__device__ __forceinline__ uint32_t tb256(int row, int col2) {
    return (uint32_t)(row * 256 + (col2 ^ ((row & 7) << 4)));
}

__device__ __forceinline__ uint32_t smem_u32(const void* p) {
    uint32_t a;
    asm("{ .reg .u64 t; cvta.to.shared.u64 t, %1; cvt.u32.u64 %0, t; }" : "=r"(a) : "l"(p));
    return a;
}

__device__ __forceinline__ void mma_bf16(float* d, uint32_t a0, uint32_t a1,
                                         uint32_t a2, uint32_t a3,
                                         uint32_t b0, uint32_t b1) {
    asm volatile(
        "mma.sync.aligned.m16n8k16.row.col.f32.bf16.bf16.f32 "
        "{%0,%1,%2,%3}, {%4,%5,%6,%7}, {%8,%9}, {%0,%1,%2,%3};"
        : "+f"(d[0]), "+f"(d[1]), "+f"(d[2]), "+f"(d[3])
        : "r"(a0), "r"(a1), "r"(a2), "r"(a3), "r"(b0), "r"(b1));
}

#define LDSM_X4(r0, r1, r2, r3, a) \
    asm volatile("ldmatrix.sync.aligned.m8n8.x4.shared.b16 {%0,%1,%2,%3}, [%4];" \
                 : "=r"(r0), "=r"(r1), "=r"(r2), "=r"(r3) : "r"(a))
#define LDSM_X4_T(r0, r1, r2, r3, a) \
    asm volatile("ldmatrix.sync.aligned.m8n8.x4.trans.shared.b16 {%0,%1,%2,%3}, [%4];" \
                 : "=r"(r0), "=r"(r1), "=r"(r2), "=r"(r3) : "r"(a))

// ---------------------------------------------------------------------------
// Kernel 1: bf16 Gram via mma.sync (unchanged from passing round-6 version).
// ---------------------------------------------------------------------------
__global__ __launch_bounds__(256) void k_gram_mma(const float* __restrict__ X,
                                                  const float* __restrict__ R) {
    __shared__ __align__(16) char s_tile[2][64 * 128];

    const int tid  = threadIdx.x;
    const int lane = tid & 31;
    const int w    = tid >> 5;       // warp 0..7
    const int m    = w & 3;          // M-strip (rows 16m..16m+15)
    const int h    = w >> 2;         // K-half (k 32h..32h+31 within chunk)
    const int grp  = lane >> 2;      // 0..7
    const int th4  = lane & 3;       // 0..3

    const int r = tid >> 2;          // staging: P row 0..63
    const int q = tid & 3;
    const size_t base = (size_t)blockIdx.x * KLOC;
    const float* src = (r < 32 ? X + (size_t)r * DD : R + (size_t)(r - 32) * DD) + base;

    float d[8][4];
#pragma unroll
    for (int n = 0; n < 8; n++)
#pragma unroll
        for (int e = 0; e < 4; e++) d[n][e] = 0.f;

    float4 v[4];
#pragma unroll
    for (int s = 0; s < 4; s++) v[s] = *(const float4*)(src + q * 4 + s * 16);

#pragma unroll
    for (int s = 0; s < 4; s++) {
        __nv_bfloat162 ab = __float22bfloat162_rn(make_float2(v[s].x, v[s].y));
        __nv_bfloat162 cd = __float22bfloat162_rn(make_float2(v[s].z, v[s].w));
        unsigned long long pk = (unsigned long long)(*(uint32_t*)&ab) |
                                ((unsigned long long)(*(uint32_t*)&cd) << 32);
        *(unsigned long long*)(s_tile[0] + tile_byte(r, q * 8 + s * 32)) = pk;
    }
    __syncthreads();

    for (int c = 0; c < NCH; c++) {
        const int buf = c & 1;

        if (c + 1 < NCH) {
            const float* p = src + (c + 1) * CHUNK;
#pragma unroll
            for (int s = 0; s < 4; s++) v[s] = *(const float4*)(p + q * 4 + s * 16);
        }

        const char* tb = s_tile[buf];
#pragma unroll
        for (int step = 0; step < 2; step++) {
            const int k0 = h * 32 + step * 16;
            const int row0 = 16 * m + grp;
            const int colA2 = (k0 + th4 * 2) * 2;
            const uint32_t a0 = *(const uint32_t*)(tb + tile_byte(row0,     colA2));
            const uint32_t a1 = *(const uint32_t*)(tb + tile_byte(row0 + 8, colA2));
            const uint32_t a2 = *(const uint32_t*)(tb + tile_byte(row0,     colA2 + 16));
            const uint32_t a3 = *(const uint32_t*)(tb + tile_byte(row0 + 8, colA2 + 16));
#pragma unroll
            for (int n = 0; n < 8; n++) {
                const int brow = 8 * n + grp;
                const uint32_t b0 = *(const uint32_t*)(tb + tile_byte(brow, colA2));
                const uint32_t b1 = *(const uint32_t*)(tb + tile_byte(brow, colA2 + 16));
                mma_bf16(d[n], a0, a1, a2, a3, b0, b1);
            }
        }

        if (c + 1 < NCH) {
            char* nb = s_tile[buf ^ 1];
#pragma unroll
            for (int s = 0; s < 4; s++) {
                __nv_bfloat162 ab = __float22bfloat162_rn(make_float2(v[s].x, v[s].y));
                __nv_bfloat162 cd = __float22bfloat162_rn(make_float2(v[s].z, v[s].w));
                unsigned long long pk = (unsigned long long)(*(uint32_t*)&ab) |
                                        ((unsigned long long)(*(uint32_t*)&cd) << 32);
                *(unsigned long long*)(nb + tile_byte(r, q * 8 + s * 32)) = pk;
            }
        }
        __syncthreads();
    }

    float* p = g_part2 + ((size_t)blockIdx.x * 2 + h) * 4096;
#pragma unroll
    for (int n = 0; n < 8; n++) {
        const int row = 16 * m + grp;
        const int col = 8 * n + th4 * 2;
        *(float2*)(p + row * 64 + col)       = make_float2(d[n][0], d[n][1]);
        *(float2*)(p + (row + 8) * 64 + col) = make_float2(d[n][2], d[n][3]);
    }
}

// ---------------------------------------------------------------------------
// Kernel 1b: reduce 1024 64x64 partials -> g_gram. Deterministic.
// ---------------------------------------------------------------------------
__global__ __launch_bounds__(256) void k_reduce() {
    __shared__ float red[8][33];
    const int part = threadIdx.x >> 5;
    const int jj   = threadIdx.x & 31;
    const int o    = blockIdx.x * 32 + jj;
    const int mtx  = o >> 10;
    const int i    = (o >> 5) & 31;
    const int j    = o & 31;
    const int src  = (mtx == 0) ? (i * 64 + j)
                   : (mtx == 1) ? (i * 64 + 32 + j)
                                : ((32 + i) * 64 + 32 + j);

    const int per = NPART / 8;
    const int b0  = part * per;
    float s0 = 0.f, s1 = 0.f, s2 = 0.f, s3 = 0.f;
#pragma unroll 4
    for (int b = 0; b < per; b += 4) {
        s0 += g_part2[(size_t)(b0 + b + 0) * 4096 + src];
        s1 += g_part2[(size_t)(b0 + b + 1) * 4096 + src];
        s2 += g_part2[(size_t)(b0 + b + 2) * 4096 + src];
        s3 += g_part2[(size_t)(b0 + b + 3) * 4096 + src];
    }
    red[part][jj] = (s0 + s1) + (s2 + s3);
    __syncthreads();
    if (part == 0) {
        float s = 0.f;
#pragma unroll
        for (int pth = 0; pth < 8; pth++) s += red[pth][jj];
        g_gram[o] = s;
    }
}

// ---------------------------------------------------------------------------
// Kernel 2: build U, V (32x32):  out = X + clip(U@X + V@R, +-1000)
// ---------------------------------------------------------------------------
__global__ __launch_bounds__(1024) void k_small(const float* __restrict__ gloss,
                                                const int* __restrict__ epoch_p) {
    __shared__ float sXX[1024], sXR[1024], sRR[1024];
    __shared__ float sXG[1024], sGG[1024], sPD[1024];
    __shared__ float sSq[32], sGn2[32], sdXG[32], sCoef[32];
    __shared__ float sRowC[32], sRowK[32], sRowA[32];
    __shared__ float sMed[2];

    const int t = threadIdx.x;
    const int i = t >> 5;
    const int j = t & 31;

    int eraw = *epoch_p;
    if (eraw > 1000000 || eraw < 0) eraw = (int)__int_as_float(eraw);
    const bool late = (eraw >= 150);

    sXX[t] = g_gram[t];
    sXR[t] = g_gram[1024 + t];
    sRR[t] = g_gram[2048 + t];
    __syncthreads();

    float xg, gg;
    if (late) { xg = sXR[t]; gg = sRR[t]; }
    else {
        xg = sXR[t] + WDC * sXX[t];
        gg = sRR[t] + WDC * (sXR[t] + sXR[j * 32 + i]) + WDC * WDC * sXX[t];
    }
    sXG[t] = xg; sGG[t] = gg;
    __syncthreads();

    if (t < 32) {
        sSq[t]   = sXX[t * 33];
        sGn2[t]  = sGG[t * 33];
        sdXG[t]  = sXG[t * 33];
        sCoef[t] = (sRR[t * 33] + WDC * sXR[t * 33]) / sGG[t * 33];
    }
    __syncthreads();

    const float pd = fmaxf(sSq[i] + sSq[j] - 2.f * sXX[t], 0.f);
    sPD[t] = pd;
    __syncthreads();

    int less = 0, leq = 0;
    const float4* p4 = (const float4*)sPD;
#pragma unroll 4
    for (int s = 0; s < 256; s++) {
        const float4 v = p4[s];
        less += (v.x <  pd) + (v.y <  pd) + (v.z <  pd) + (v.w <  pd);
        leq  += (v.x <= pd) + (v.y <= pd) + (v.z <= pd) + (v.w <= pd);
    }
    if (less <= 511 && 511 < leq) sMed[0] = pd;
    if (less <= 512 && 512 < leq) sMed[1] = pd;
    __syncthreads();

    const float hk = (sMed[0] + sMed[1]) * 0.5f / 3.4657359027997265f + 1e-6f;
    const float Kv = expf(-pd / hk);
    const float Cv = 2.f * Kv / hk;

    const float Av = Cv * (sdXG[i] - sXG[j * 32 + i]) / sGn2[i];
    float rc = Cv, rk = Kv, ra = Av;
#pragma unroll
    for (int off = 16; off; off >>= 1) {
        rc += __shfl_xor_sync(0xffffffffu, rc, off);
        rk += __shfl_xor_sync(0xffffffffu, rk, off);
        ra += __shfl_xor_sync(0xffffffffu, ra, off);
    }
    if (j == 0) { sRowC[i] = rc; sRowK[i] = rk; sRowA[i] = ra; }

    const float Bv = (Cv * (xg - sdXG[j]) - Av * gg) / sGn2[j];
    float Mv = 0.f;
    if (late) {
        const float coef = sCoef[i];
        const float sgt  = WDC * xg + (1.f - coef) * gg;
        Mv = Kv * sgt / sGn2[j];
    }
    __syncthreads();

    float Ux = -Cv;
    float Vg = -Bv - Mv;
    if (i == j) {
        Ux += sRowC[i] + (late ? WDC * sRowK[i] : 0.f);
        Vg += -sRowA[i] + (late ? (1.f - sCoef[i]) * sRowK[i] : 0.f);
    }
    const float sc = LR_C / (float)NP;
    float U = Ux * sc;
    float V = Vg * sc;
    if (i == j) {
        const float gl = gloss[i];
        const float sg = (gl > 0.f) ? 1.f : ((gl < 0.f) ? -1.f : 0.f);
        V -= LR_C * ALPHA_C * sg;
    }
    if (!late) U += WDC * V;

    g_UT[j * 32 + i] = U;
    g_VT[j * 32 + i] = V;
}

// ---------------------------------------------------------------------------
// Kernel 3: out = X + clip(W@P) via mma.sync.
// W = [U|V] 32x64 bf16 (A operand), P = [X;R] 64 x 128-col tile bf16 (B via
// ldmatrix.trans). fp32 X added in epilogue. Grid = D/128, 256 threads.
// ---------------------------------------------------------------------------
__global__ __launch_bounds__(256) void k_apply_mma(const float* __restrict__ X,
                                                   const float* __restrict__ R,
                                                   float* __restrict__ out) {
    __shared__ __align__(16) char sB[64 * 256];   // bf16 [64 j][128 col], 256B rows
    __shared__ __align__(16) char sA[32 * 128];   // bf16 W [32 i][64 j], 128B rows

    const int tid  = threadIdx.x;
    const int lane = tid & 31;
    const int w    = tid >> 5;         // warp: cols [16w, 16w+16)
    const int grp  = lane >> 2;
    const int th4  = lane & 3;

    // build W tile (bf16): W[i][j] = j<32 ? U[i][j] : V[i][j-32]
#pragma unroll
    for (int e = tid; e < 2048; e += 256) {
        const int j = e >> 5, i = e & 31;
        const float wv = (j < 32) ? g_UT[j * 32 + i] : g_VT[(j - 32) * 32 + i];
        const __nv_bfloat16 b = __float2bfloat16(wv);
        *(uint16_t*)(sA + tile_byte(i, 2 * j)) = *(const uint16_t*)&b;
    }

    // stage P tile: thread -> row r (0..63), 32 cols
    const int r = tid >> 2;
    const int q = tid & 3;
    const size_t colbase = (size_t)blockIdx.x * 128;
    const float* src = (r < 32 ? X + (size_t)r * DD : R + (size_t)(r - 32) * DD) + colbase;
#pragma unroll
    for (int s = 0; s < 8; s++) {
        const int col = q * 4 + s * 16;
        const float4 v = *(const float4*)(src + col);
        __nv_bfloat162 ab = __float22bfloat162_rn(make_float2(v.x, v.y));
        __nv_bfloat162 cd = __float22bfloat162_rn(make_float2(v.z, v.w));
        unsigned long long pk = (unsigned long long)(*(uint32_t*)&ab) |
                                ((unsigned long long)(*(uint32_t*)&cd) << 32);
        *(unsigned long long*)(sB + tb256(r, col * 2)) = pk;
    }
    __syncthreads();

    const uint32_t sA32 = smem_u32(sA);
    const uint32_t sB32 = smem_u32(sB);

    float acc[2][2][4];
#pragma unroll
    for (int mi = 0; mi < 2; mi++)
#pragma unroll
        for (int ni = 0; ni < 2; ni++)
#pragma unroll
            for (int e = 0; e < 4; e++) acc[mi][ni][e] = 0.f;

#pragma unroll
    for (int ks = 0; ks < 4; ks++) {
        const int k0 = ks * 16;

        // A fragments: non-trans x4 per m-tile
        uint32_t a[2][4];
#pragma unroll
        for (int mi = 0; mi < 2; mi++) {
            const int arow = 16 * mi + (lane & 7) + ((lane >> 3) & 1) * 8;
            const int acol2 = (k0 + (lane >> 4) * 8) * 2;
            LDSM_X4(a[mi][0], a[mi][1], a[mi][2], a[mi][3], sA32 + tile_byte(arow, acol2));
        }

        // B fragments: x4.trans — tiles (kLo,n0),(kHi,n0),(kLo,n1),(kHi,n1)
        const int til  = lane >> 3;
        const int brow = k0 + (til & 1) * 8 + (lane & 7);
        const int bcol2 = (w * 16 + (til >> 1) * 8) * 2;
        uint32_t bb0, bb1, bb2, bb3;
        LDSM_X4_T(bb0, bb1, bb2, bb3, sB32 + tb256(brow, bcol2));

#pragma unroll
        for (int mi = 0; mi < 2; mi++) {
            mma_bf16(acc[mi][0], a[mi][0], a[mi][1], a[mi][2], a[mi][3], bb0, bb1);
            mma_bf16(acc[mi][1], a[mi][0], a[mi][1], a[mi][2], a[mi][3], bb2, bb3);
        }
    }

    // epilogue: out = X + clip(acc). X re-read is L2-hot (staged moments ago).
#pragma unroll
    for (int mi = 0; mi < 2; mi++) {
#pragma unroll
        for (int ni = 0; ni < 2; ni++) {
            const int i0 = 16 * mi + grp;
            const size_t c = colbase + w * 16 + ni * 8 + 2 * th4;
            const float2 x0 = *(const float2*)(X + (size_t)i0 * DD + c);
            const float2 x1 = *(const float2*)(X + (size_t)(i0 + 8) * DD + c);
            float2 o0, o1;
            o0.x = x0.x + fminf(fmaxf(acc[mi][ni][0], -1000.f), 1000.f);
            o0.y = x0.y + fminf(fmaxf(acc[mi][ni][1], -1000.f), 1000.f);
            o1.x = x1.x + fminf(fmaxf(acc[mi][ni][2], -1000.f), 1000.f);
            o1.y = x1.y + fminf(fmaxf(acc[mi][ni][3], -1000.f), 1000.f);
            *(float2*)(out + (size_t)i0 * DD + c) = o0;
            *(float2*)(out + (size_t)(i0 + 8) * DD + c) = o1;
        }
    }
}

// ---------------------------------------------------------------------------
extern "C" void kernel_launch(void* const* d_in, const int* in_sizes, int n_in,
                              void* d_out, int out_size) {
    const float* X  = (const float*)d_in[0];
    const float* R  = (const float*)d_in[1];
    const float* gl = (const float*)d_in[2];
    const int*   ep = (const int*)d_in[3];
    float* out = (float*)d_out;

    k_gram_mma<<<GCTA, 256>>>(X, R);
    k_reduce<<<96, 256>>>();
    k_small<<<1, 1024>>>(gl, ep);
    k_apply_mma<<<DD / 128, 256>>>(X, R, out);
}